// round 17
// baseline (speedup 1.0000x reference)
#include <cuda_runtime.h>
#include <cuda_bf16.h>
#include <cuda_fp16.h>
#include <cstdint>

// Problem constants
#define M_ROWS 16384          // B_SZ * SEQ
#define K_IN   4096           // D_IN
#define N_OUT  4096           // D_OUT
#define R_LORA 64
#define K_TOP  16
#define K_EXT  4160           // K_IN + R_LORA
#define SCALE_F 2.0f          // ALPHA / R
#define KB16   (K_EXT / 16)   // 260 k-blocks of 16

// GEMM tiling
#define BM 128
#define BN 256
#define NSTAGE 5
#define KTILES (K_EXT / 32)        // 130 (two kb16 per ktile)
#define A_ST_BYTES 8192            // 8 mt * 2 kb * 512B
#define B_ST_BYTES 16384           // 16 nt * 2 kb * 512B
#define STAGE_BYTES (A_ST_BYTES + B_ST_BYTES)   // 24576
#define GRID_TILES ((M_ROWS / BM) * (N_OUT / BN))   // 128*16 = 2048

// Scratch (device globals: allocation-free), fp16 fragment-major.
// g_xa: A' [mt(1024)][kb16(260)][lane(32)] uint4 = {a0,a1,a2,a3} of m16n8k16:
//   a0={A[gr][2tg],A[gr][2tg+1]} a1={A[gr+8][2tg..]} a2={A[gr][2tg+8..]} a3={A[gr+8][2tg+8..]}
// g_wb: B' [nt16(256)][kb16(260)][lane] uint4 = {b0,b1 of n8-block0, b0,b1 of n8-block1}:
//   q0={W[gr][2tg..]} q1={W[gr][2tg+8..]} q2={W[gr+8][2tg..]} q3={W[gr+8][2tg+8..]}
__device__ __half g_xa[(size_t)M_ROWS * K_EXT];
__device__ __half g_wb[(size_t)N_OUT * K_EXT];
__device__ float  g_zp[4ull * M_ROWS * R_LORA];   // split-K partials of z (fp32)

__device__ __forceinline__ uint32_t packh2(float lo, float hi) {
    __half2 h = __floats2half2_rn(lo, hi);
    return *(uint32_t*)&h;
}

// ---------------------------------------------------------------------------
// cvt_x: fp32 x -> fp16 fragment-major A' (k < 4096).  block = mt x 256k.
// ---------------------------------------------------------------------------
__global__ __launch_bounds__(256) void cvt_x_kernel(const float4* __restrict__ in) {
    __shared__ float s[16][260];
    const int t  = threadIdx.x;
    const int mt = blockIdx.x >> 4;
    const int kc = blockIdx.x & 15;

#pragma unroll
    for (int p = 0; p < 4; p++) {
        int idx = t + p * 256;              // 0..1023
        int row = idx >> 6;                 // 0..15
        int kq  = idx & 63;
        float4 v = in[((size_t)(mt * 16 + row) * K_IN + kc * 256) / 4 + kq];
        s[row][kq * 4 + 0] = v.x; s[row][kq * 4 + 1] = v.y;
        s[row][kq * 4 + 2] = v.z; s[row][kq * 4 + 3] = v.w;
    }
    __syncthreads();

    uint4* g4 = (uint4*)g_xa;
#pragma unroll
    for (int p = 0; p < 2; p++) {
        int idx  = t + p * 256;             // 0..511
        int kbl  = idx >> 5;                // 0..15
        int lane = idx & 31;
        int gr = lane >> 2, tg = lane & 3;
        int kk = kbl * 16;
        uint4 v;
        v.x = packh2(s[gr    ][kk + 2 * tg    ], s[gr    ][kk + 2 * tg + 1]);
        v.y = packh2(s[gr + 8][kk + 2 * tg    ], s[gr + 8][kk + 2 * tg + 1]);
        v.z = packh2(s[gr    ][kk + 2 * tg + 8], s[gr    ][kk + 2 * tg + 9]);
        v.w = packh2(s[gr + 8][kk + 2 * tg + 8], s[gr + 8][kk + 2 * tg + 9]);
        g4[((size_t)mt * KB16 + kc * 16 + kbl) * 32 + lane] = v;
    }
}

// ---------------------------------------------------------------------------
// cvt_w: fp32 W -> fp16 fragment-major B' (k < 4096).  block = nt16 x 256k.
// ---------------------------------------------------------------------------
__global__ __launch_bounds__(256) void cvt_w_kernel(const float4* __restrict__ in) {
    __shared__ float s[16][260];
    const int t  = threadIdx.x;
    const int nt = blockIdx.x >> 4;
    const int kc = blockIdx.x & 15;

#pragma unroll
    for (int p = 0; p < 4; p++) {
        int idx = t + p * 256;
        int row = idx >> 6;
        int kq  = idx & 63;
        float4 v = in[((size_t)(nt * 16 + row) * K_IN + kc * 256) / 4 + kq];
        s[row][kq * 4 + 0] = v.x; s[row][kq * 4 + 1] = v.y;
        s[row][kq * 4 + 2] = v.z; s[row][kq * 4 + 3] = v.w;
    }
    __syncthreads();

    uint4* g4 = (uint4*)g_wb;
#pragma unroll
    for (int p = 0; p < 2; p++) {
        int idx  = t + p * 256;
        int kbl  = idx >> 5;
        int lane = idx & 31;
        int gr = lane >> 2, tg = lane & 3;
        int kk = kbl * 16;
        uint4 v;
        v.x = packh2(s[gr    ][kk + 2 * tg    ], s[gr    ][kk + 2 * tg + 1]);
        v.y = packh2(s[gr    ][kk + 2 * tg + 8], s[gr    ][kk + 2 * tg + 9]);
        v.z = packh2(s[gr + 8][kk + 2 * tg    ], s[gr + 8][kk + 2 * tg + 1]);
        v.w = packh2(s[gr + 8][kk + 2 * tg + 8], s[gr + 8][kk + 2 * tg + 9]);
        g4[((size_t)nt * KB16 + kc * 16 + kbl) * 32 + lane] = v;
    }
}

// ---------------------------------------------------------------------------
// cvt_b: LoRA B (4096 x 64) -> fp16 B' extension (kb16 256..259).
// block = 64 n-rows (4 nt16) x 64 r.  grid = 64.
// ---------------------------------------------------------------------------
__global__ __launch_bounds__(256) void cvt_b_kernel(const float4* __restrict__ in) {
    __shared__ float s[64][68];
    const int t   = threadIdx.x;
    const int n0t = blockIdx.x * 4;     // first nt16 tile

#pragma unroll
    for (int p = 0; p < 4; p++) {
        int idx = t + p * 256;          // 0..1023 float4s (64 rows x 16)
        int row = idx >> 4;
        int kq  = idx & 15;
        float4 v = in[((size_t)(n0t * 16 + row) * R_LORA) / 4 + kq];
        s[row][kq * 4 + 0] = v.x; s[row][kq * 4 + 1] = v.y;
        s[row][kq * 4 + 2] = v.z; s[row][kq * 4 + 3] = v.w;
    }
    __syncthreads();

    uint4* g4 = (uint4*)g_wb;
#pragma unroll
    for (int p = 0; p < 2; p++) {
        int idx  = t + p * 256;         // 0..511
        int blk  = idx >> 5;            // 0..15 = ntl*4 + kbl
        int ntl  = blk >> 2;
        int kbl  = blk & 3;
        int lane = idx & 31;
        int gr = lane >> 2, tg = lane & 3;
        int r0 = ntl * 16;
        int kk = kbl * 16;
        uint4 v;
        v.x = packh2(s[r0 + gr    ][kk + 2 * tg    ], s[r0 + gr    ][kk + 2 * tg + 1]);
        v.y = packh2(s[r0 + gr    ][kk + 2 * tg + 8], s[r0 + gr    ][kk + 2 * tg + 9]);
        v.z = packh2(s[r0 + gr + 8][kk + 2 * tg    ], s[r0 + gr + 8][kk + 2 * tg + 1]);
        v.w = packh2(s[r0 + gr + 8][kk + 2 * tg + 8], s[r0 + gr + 8][kk + 2 * tg + 9]);
        g4[((size_t)(n0t + ntl) * KB16 + 256 + kbl) * 32 + lane] = v;
    }
}

// ---------------------------------------------------------------------------
// z = x @ A^T in fp32 (accuracy needed for correct top-k selection).
// Split-K=4, deterministic partial buffers.
// ---------------------------------------------------------------------------
__global__ __launch_bounds__(128) void z_partial(const float* __restrict__ x,
                                                 const float* __restrict__ Amat) {
    __shared__ float xsT[32][132];
    __shared__ float asT[32][68];

    const int t  = threadIdx.x;
    const int m0 = blockIdx.x * 128;
    const int kb = blockIdx.y * 1024;
    const int tm = t >> 3;
    const int tr = t & 7;

    float acc[8][8];
#pragma unroll
    for (int i = 0; i < 8; i++)
#pragma unroll
        for (int j = 0; j < 8; j++) acc[i][j] = 0.0f;

    for (int kc = 0; kc < 1024; kc += 32) {
        const int k0 = kb + kc;
        const int kk0 = (t & 7) << 2;
#pragma unroll
        for (int i = 0; i < 8; i++) {
            int r = (t >> 3) + i * 16;
            float4 v = *(const float4*)&x[(size_t)(m0 + r) * K_IN + k0 + kk0];
            xsT[kk0 + 0][r] = v.x; xsT[kk0 + 1][r] = v.y;
            xsT[kk0 + 2][r] = v.z; xsT[kk0 + 3][r] = v.w;
        }
#pragma unroll
        for (int i = 0; i < 4; i++) {
            int r = (t >> 3) + i * 16;
            float4 v = *(const float4*)&Amat[(size_t)r * K_IN + k0 + kk0];
            asT[kk0 + 0][r] = v.x; asT[kk0 + 1][r] = v.y;
            asT[kk0 + 2][r] = v.z; asT[kk0 + 3][r] = v.w;
        }
        __syncthreads();
#pragma unroll
        for (int kk = 0; kk < 32; kk++) {
            float av[8], bv[8];
            *(float4*)&av[0] = *(const float4*)&xsT[kk][tm * 8];
            *(float4*)&av[4] = *(const float4*)&xsT[kk][tm * 8 + 4];
            *(float4*)&bv[0] = *(const float4*)&asT[kk][tr * 8];
            *(float4*)&bv[4] = *(const float4*)&asT[kk][tr * 8 + 4];
#pragma unroll
            for (int i = 0; i < 8; i++)
#pragma unroll
                for (int j = 0; j < 8; j++)
                    acc[i][j] = fmaf(av[i], bv[j], acc[i][j]);
        }
        __syncthreads();
    }

    float* zp = g_zp + (size_t)blockIdx.y * M_ROWS * R_LORA;
#pragma unroll
    for (int i = 0; i < 8; i++)
#pragma unroll
        for (int j = 0; j < 8; j++)
            zp[(size_t)(m0 + tm * 8 + i) * R_LORA + tr * 8 + j] = acc[i][j];
}

// ---------------------------------------------------------------------------
// Top-k (k=16 of 64): keep iff #{j: az_j > az_i} < 16.
// Writes SCALE*z (fp16) into the fragment-major extension block of g_xa.
// ---------------------------------------------------------------------------
__global__ void topk_kernel() {
    __shared__ float az[4][64];
    const int sub = threadIdx.x >> 6;
    const int j   = threadIdx.x & 63;
    const int row = blockIdx.x * 4 + sub;

    const size_t ZP = (size_t)M_ROWS * R_LORA;
    const size_t base = (size_t)row * R_LORA + j;
    float v = ((g_zp[base] + g_zp[base + ZP]) + g_zp[base + 2 * ZP]) + g_zp[base + 3 * ZP];
    float a = fabsf(v);
    az[sub][j] = a;
    __syncthreads();

    int cnt = 0;
#pragma unroll
    for (int t = 0; t < 64; t++) cnt += (az[sub][t] > a) ? 1 : 0;

    // fragment-major fp16 address within g_xa (A' layout, m16n8k16)
    const int mt = row >> 4, mr = row & 15;
    const int kb = 256 + (j >> 4);
    const int kl = j & 15;
    const int gr = mr & 7;
    const int tg = (kl & 7) >> 1;
    const int q  = ((kl >> 3) << 1) + (mr >> 3);
    const int lane = gr * 4 + tg;
    size_t idx = ((((size_t)mt * KB16 + kb) * 32 + lane) << 3) + (q << 1) + (kl & 1);
    g_xa[idx] = __float2half_rn((cnt < K_TOP) ? v * SCALE_F : 0.0f);
}

// ---------------------------------------------------------------------------
// Main GEMM: out[m,n] = sum_k x*w + bias.  fp16 mma.sync m16n8k16, fp32 accum.
// CTA 128x256x32, warp tile 64x64, fragment-major smem, LDS.128 only.
// ---------------------------------------------------------------------------
__device__ __forceinline__ void cp_async16(uint32_t smem_addr, const void* gptr) {
    asm volatile("cp.async.cg.shared.global [%0], [%1], 16;\n"
                 :: "r"(smem_addr), "l"(gptr));
}

__device__ __forceinline__ void mma_h(float* c, const uint4& a, uint32_t b0, uint32_t b1) {
    asm volatile(
        "mma.sync.aligned.m16n8k16.row.col.f32.f16.f16.f32 "
        "{%0,%1,%2,%3}, {%4,%5,%6,%7}, {%8,%9}, {%0,%1,%2,%3};\n"
        : "+f"(c[0]), "+f"(c[1]), "+f"(c[2]), "+f"(c[3])
        : "r"(a.x), "r"(a.y), "r"(a.z), "r"(a.w), "r"(b0), "r"(b1));
}

__global__ __launch_bounds__(256, 1) void gemm_kernel(const float* __restrict__ bias,
                                                      float* __restrict__ out) {
    extern __shared__ uint4 sm4[];

    const int t    = threadIdx.x;
    const int lane = t & 31;
    const int wid  = t >> 5;
    const int wm   = wid & 1;          // 2 warps in m (64 rows each)
    const int wn   = wid >> 1;         // 4 warps in n (64 cols each)

    // L2-friendly rasterization: supertiles of 8 bm x 16 bn
    const int pid = blockIdx.x;
    const int grp = pid >> 7;                // 0..15
    const int loc = pid & 127;
    const int bm  = grp * 8 + (loc & 7);     // 0..127
    const int bn  = loc >> 3;                // 0..15

    const uint4* gA = (const uint4*)g_xa;
    const uint4* gB = (const uint4*)g_wb;
    const uint32_t sbase = (uint32_t)__cvta_generic_to_shared(sm4);

    // per-thread cp.async descriptors (uint4 index at kt=0, smem byte offset)
    size_t aG[2]; uint32_t aS[2];
#pragma unroll
    for (int i = 0; i < 2; i++) {
        int ia   = t + i * 256;              // 0..511
        int blk  = ia >> 5;                  // mtl*2 + kbl
        int lc   = ia & 31;
        int mtl  = blk >> 1, kbl = blk & 1;
        aG[i] = ((size_t)(bm * 8 + mtl) * KB16 + kbl) * 32 + lc;
        aS[i] = (uint32_t)(ia * 16);
    }
    size_t bG[4]; uint32_t bS[4];
#pragma unroll
    for (int i = 0; i < 4; i++) {
        int ib   = t + i * 256;              // 0..1023
        int blk  = ib >> 5;                  // ntl*2 + kbl
        int lc   = ib & 31;
        int ntl  = blk >> 1, kbl = blk & 1;
        bG[i] = ((size_t)(bn * 16 + ntl) * KB16 + kbl) * 32 + lc;
        bS[i] = (uint32_t)(A_ST_BYTES + ib * 16);
    }

    // prologue: stages 0..NSTAGE-2
#pragma unroll
    for (int s = 0; s < NSTAGE - 1; s++) {
        uint32_t so = sbase + s * STAGE_BYTES;
#pragma unroll
        for (int i = 0; i < 2; i++) cp_async16(so + aS[i], gA + aG[i] + (size_t)s * 64);
#pragma unroll
        for (int i = 0; i < 4; i++) cp_async16(so + bS[i], gB + bG[i] + (size_t)s * 64);
        asm volatile("cp.async.commit_group;\n");
    }

    float c[4][8][4];
#pragma unroll
    for (int mf = 0; mf < 4; mf++)
#pragma unroll
        for (int nf = 0; nf < 8; nf++)
#pragma unroll
            for (int q = 0; q < 4; q++) c[mf][nf][q] = 0.0f;

    for (int kt = 0; kt < KTILES; kt++) {
        asm volatile("cp.async.wait_group 3;\n");
        __syncthreads();

        const int kf = kt + NSTAGE - 1;
        if (kf < KTILES) {
            uint32_t so = sbase + (kf % NSTAGE) * STAGE_BYTES;
#pragma unroll
            for (int i = 0; i < 2; i++) cp_async16(so + aS[i], gA + aG[i] + (size_t)kf * 64);
#pragma unroll
            for (int i = 0; i < 4; i++) cp_async16(so + bS[i], gB + bG[i] + (size_t)kf * 64);
        }
        asm volatile("cp.async.commit_group;\n");

        const uint4* As4 = sm4 + (size_t)(kt % NSTAGE) * (STAGE_BYTES / 16);
        const uint4* Bs4 = As4 + (A_ST_BYTES / 16);

#pragma unroll
        for (int kbl = 0; kbl < 2; kbl++) {
            uint4 af[4], bf[4];
#pragma unroll
            for (int mf = 0; mf < 4; mf++)
                af[mf] = As4[((wm * 4 + mf) * 2 + kbl) * 32 + lane];
#pragma unroll
            for (int np = 0; np < 4; np++)
                bf[np] = Bs4[((wn * 4 + np) * 2 + kbl) * 32 + lane];
#pragma unroll
            for (int mf = 0; mf < 4; mf++)
#pragma unroll
                for (int np = 0; np < 4; np++) {
                    mma_h(c[mf][2 * np],     af[mf], bf[np].x, bf[np].y);
                    mma_h(c[mf][2 * np + 1], af[mf], bf[np].z, bf[np].w);
                }
        }
    }

    // epilogue: add bias, write fp32
    const int gr = lane >> 2, tg = lane & 3;
#pragma unroll
    for (int mf = 0; mf < 4; mf++) {
        const int row = bm * BM + wm * 64 + mf * 16 + gr;
#pragma unroll
        for (int nf = 0; nf < 8; nf++) {
            const int col = bn * BN + wn * 64 + (nf >> 1) * 16 + (nf & 1) * 8 + tg * 2;
            const float b0 = __ldg(&bias[col]);
            const float b1 = __ldg(&bias[col + 1]);
            float2 v0 = make_float2(c[mf][nf][0] + b0, c[mf][nf][1] + b1);
            float2 v1 = make_float2(c[mf][nf][2] + b0, c[mf][nf][3] + b1);
            *(float2*)&out[(size_t)row * N_OUT + col] = v0;
            *(float2*)&out[(size_t)(row + 8) * N_OUT + col] = v1;
        }
    }
}

// ---------------------------------------------------------------------------
extern "C" void kernel_launch(void* const* d_in, const int* in_sizes, int n_in,
                              void* d_out, int out_size) {
    const float* x    = (const float*)d_in[0];
    const float* W    = (const float*)d_in[1];
    const float* bias = (const float*)d_in[2];
    const float* A    = (const float*)d_in[3];
    const float* Bm   = (const float*)d_in[4];
    float* out = (float*)d_out;

    cudaFuncSetAttribute(gemm_kernel, cudaFuncAttributeMaxDynamicSharedMemorySize,
                         NSTAGE * STAGE_BYTES);

    cvt_x_kernel<<<16384, 256>>>((const float4*)x);
    cvt_w_kernel<<<4096, 256>>>((const float4*)W);
    cvt_b_kernel<<<64, 256>>>((const float4*)Bm);
    z_partial<<<dim3(128, 4), 128>>>(x, A);
    topk_kernel<<<4096, 256>>>();
    gemm_kernel<<<GRID_TILES, 256, NSTAGE * STAGE_BYTES>>>(bias, out);
}